// round 1
// baseline (speedup 1.0000x reference)
#include <cuda_runtime.h>

#define HID 24
#define NP  36      // 72 gate rows / 2 (f32x2 pairs)
#define TPB 128

typedef unsigned long long u64;

__device__ __forceinline__ u64 pack2(float x, float y) {
    u64 r; asm("mov.b64 %0, {%1, %2};" : "=l"(r) : "f"(x), "f"(y)); return r;
}
__device__ __forceinline__ void unpack2(u64 v, float &x, float &y) {
    asm("mov.b64 {%0, %1}, %2;" : "=f"(x), "=f"(y) : "l"(v));
}
__device__ __forceinline__ u64 ffma2(u64 a, u64 b, u64 c) {
    u64 d; asm("fma.rn.f32x2 %0, %1, %2, %3;" : "=l"(d) : "l"(a), "l"(b), "l"(c)); return d;
}
__device__ __forceinline__ u64 fmul2(u64 a, u64 b) {
    u64 d; asm("mul.rn.f32x2 %0, %1, %2;" : "=l"(d) : "l"(a), "l"(b)); return d;
}
__device__ __forceinline__ float ex2a(float x) {
    float r; asm("ex2.approx.f32 %0, %1;" : "=f"(r) : "f"(x)); return r;
}
__device__ __forceinline__ float rcpa(float x) {
    float r; asm("rcp.approx.f32 %0, %1;" : "=f"(r) : "f"(x)); return r;
}

// sigmoid(v) = 1 / (1 + 2^(-v*log2(e)))
__device__ __forceinline__ float sig_f(float v) {
    return rcpa(1.0f + ex2a(v * -1.442695041f));
}
// tanh(v) = 2 / (1 + 2^(-2v*log2(e))) - 1
__device__ __forceinline__ float tanh_f(float v) {
    return fmaf(2.0f, rcpa(1.0f + ex2a(v * -2.885390082f)), -1.0f);
}

__global__ void __launch_bounds__(TPB)
trendgru_kernel(const float* __restrict__ x,
                const float* __restrict__ W_ih,
                const float* __restrict__ b_ih,
                const float* __restrict__ W_hh,
                const float* __restrict__ b_hh,
                const float* __restrict__ fc_w,
                const float* __restrict__ fc_b,
                float* __restrict__ out,
                int B, int T)
{
    // W_hh repacked k-major as f32x2 pairs along the gate dim:
    // Wp[k][j] = ( W_hh[2j][k], W_hh[2j+1][k] ),  j = 0..35 (r:0-11, z:12-23, n:24-35)
    __shared__ __align__(16) u64 Wp[HID][NP];          // 6912 B
    __shared__ __align__(16) ulonglong2 initRZ[24];    // ( W_ih pair, (b_ih+b_hh) pair )
    __shared__ __align__(16) ulonglong2 initN[12];     // ( W_ih_n pair, b_ih_n pair )
    __shared__ u64 bnhh[12];                           // b_hh n-gate pairs

    const int tid = threadIdx.x;
    for (int i = tid; i < HID * NP; i += TPB) {
        int k = i / NP, j = i % NP;
        Wp[k][j] = pack2(W_hh[(2*j) * HID + k], W_hh[(2*j+1) * HID + k]);
    }
    if (tid < 24) {
        int g = 2 * tid;
        initRZ[tid].x = pack2(W_ih[g], W_ih[g+1]);
        initRZ[tid].y = pack2(b_ih[g] + b_hh[g], b_ih[g+1] + b_hh[g+1]);
    } else if (tid < 36) {
        int j = tid - 24, g = 48 + 2 * j;
        initN[j].x = pack2(W_ih[g], W_ih[g+1]);
        initN[j].y = pack2(b_ih[g], b_ih[g+1]);
        bnhh[j]    = pack2(b_hh[g], b_hh[g+1]);
    }
    __syncthreads();

    const int b = blockIdx.x * TPB + tid;
    if (b >= B) return;

    u64 h[12];
    #pragma unroll
    for (int j = 0; j < 12; j++) h[j] = 0ULL;

    const float* xrow = x + (long long)b * T;

    for (int t = 0; t < T; t++) {
        const float xv = __ldg(xrow + t);
        const u64 x2 = pack2(xv, xv);

        u64 acc[NP];
        #pragma unroll
        for (int j = 0; j < 24; j++) {          // r,z: fold input proj + both biases
            ulonglong2 w = initRZ[j];
            acc[j] = ffma2(w.x, x2, w.y);
        }
        u64 xn[12];
        #pragma unroll
        for (int j = 0; j < 12; j++) {          // n: keep xn separate (r gates hn only)
            ulonglong2 w = initN[j];
            xn[j]      = ffma2(w.x, x2, w.y);
            acc[24+j]  = bnhh[j];
        }

        // gh += W_hh . h   (864 FFMA2 per step, warp-uniform SMEM broadcast loads)
        #pragma unroll 4
        for (int p = 0; p < 12; p++) {
            float h0, h1; unpack2(h[p], h0, h1);
            const u64 ha = pack2(h0, h0);
            const u64 hb = pack2(h1, h1);
            const ulonglong2* r0 = reinterpret_cast<const ulonglong2*>(&Wp[2*p][0]);
            const ulonglong2* r1 = reinterpret_cast<const ulonglong2*>(&Wp[2*p+1][0]);
            #pragma unroll
            for (int jj = 0; jj < 18; jj++) {
                ulonglong2 w = r0[jj];
                acc[2*jj]   = ffma2(w.x, ha, acc[2*jj]);
                acc[2*jj+1] = ffma2(w.y, ha, acc[2*jj+1]);
            }
            #pragma unroll
            for (int jj = 0; jj < 18; jj++) {
                ulonglong2 w = r1[jj];
                acc[2*jj]   = ffma2(w.x, hb, acc[2*jj]);
                acc[2*jj+1] = ffma2(w.y, hb, acc[2*jj+1]);
            }
        }

        // gates + state update
        #pragma unroll
        for (int j = 0; j < 12; j++) {
            float a0, a1; unpack2(acc[j], a0, a1);
            const u64 r2 = pack2(sig_f(a0), sig_f(a1));

            float c0, c1; unpack2(acc[12+j], c0, c1);
            const float z0 = sig_f(c0), z1 = sig_f(c1);
            const u64 z2  = pack2(z0, z1);
            const u64 zc2 = pack2(1.0f - z0, 1.0f - z1);

            const u64 npre = ffma2(r2, acc[24+j], xn[j]);
            float n0p, n1p; unpack2(npre, n0p, n1p);
            const u64 n2 = pack2(tanh_f(n0p), tanh_f(n1p));

            // h = z*h + (1-z)*n
            h[j] = ffma2(z2, h[j], fmul2(zc2, n2));
        }
    }

    // final fc: out[b] = h @ fc_w.T + fc_b
    float hs[24];
    #pragma unroll
    for (int j = 0; j < 12; j++) unpack2(h[j], hs[2*j], hs[2*j+1]);
    float o0 = __ldg(fc_b + 0);
    float o1 = __ldg(fc_b + 1);
    #pragma unroll
    for (int k = 0; k < 24; k++) {
        o0 = fmaf(__ldg(fc_w + k),       hs[k], o0);
        o1 = fmaf(__ldg(fc_w + 24 + k),  hs[k], o1);
    }
    out[2*b + 0] = o0;
    out[2*b + 1] = o1;
}

extern "C" void kernel_launch(void* const* d_in, const int* in_sizes, int n_in,
                              void* d_out, int out_size)
{
    const float* x    = (const float*)d_in[0];
    const float* W_ih = (const float*)d_in[1];
    const float* b_ih = (const float*)d_in[2];
    const float* W_hh = (const float*)d_in[3];
    const float* b_hh = (const float*)d_in[4];
    const float* fc_w = (const float*)d_in[5];
    const float* fc_b = (const float*)d_in[6];
    float* out = (float*)d_out;

    const int B = out_size / 2;
    const int T = in_sizes[0] / B;

    const int grid = (B + TPB - 1) / TPB;
    trendgru_kernel<<<grid, TPB>>>(x, W_ih, b_ih, W_hh, b_hh, fc_w, fc_b, out, B, T);
}

// round 2
// speedup vs baseline: 1.0146x; 1.0146x over previous
#include <cuda_runtime.h>

#define HID 24
#define NP  36      // 72 gate rows / 2 (f32x2 pairs)
#define TPB 128

typedef unsigned long long u64;

__device__ __forceinline__ u64 pack2(float x, float y) {
    u64 r; asm("mov.b64 %0, {%1, %2};" : "=l"(r) : "f"(x), "f"(y)); return r;
}
__device__ __forceinline__ void unpack2(u64 v, float &x, float &y) {
    asm("mov.b64 {%0, %1}, %2;" : "=f"(x), "=f"(y) : "l"(v));
}
__device__ __forceinline__ u64 ffma2(u64 a, u64 b, u64 c) {
    u64 d; asm("fma.rn.f32x2 %0, %1, %2, %3;" : "=l"(d) : "l"(a), "l"(b), "l"(c)); return d;
}
__device__ __forceinline__ u64 fadd2(u64 a, u64 b) {
    u64 d; asm("add.rn.f32x2 %0, %1, %2;" : "=l"(d) : "l"(a), "l"(b)); return d;
}
__device__ __forceinline__ float ex2a(float x) {
    float r; asm("ex2.approx.f32 %0, %1;" : "=f"(r) : "f"(x)); return r;
}
__device__ __forceinline__ float rcpa(float x) {
    float r; asm("rcp.approx.f32 %0, %1;" : "=f"(r) : "f"(x)); return r;
}
// sigmoid(v) = 1 / (1 + 2^(-v*log2(e)))
__device__ __forceinline__ float sig_f(float v) {
    return rcpa(1.0f + ex2a(v * -1.442695041f));
}
// tanh(v) = 2 / (1 + 2^(-2v*log2(e))) - 1
__device__ __forceinline__ float tanh_f(float v) {
    return fmaf(2.0f, rcpa(1.0f + ex2a(v * -2.885390082f)), -1.0f);
}

__global__ void __launch_bounds__(TPB)
trendgru_kernel(const float* __restrict__ x,
                const float* __restrict__ W_ih,
                const float* __restrict__ b_ih,
                const float* __restrict__ W_hh,
                const float* __restrict__ b_hh,
                const float* __restrict__ fc_w,
                const float* __restrict__ fc_b,
                float* __restrict__ out,
                int B, int T)
{
    // W_hh k-major as f32x2 pairs along gate dim:
    // Wp[k][j] = ( W_hh[2j][k], W_hh[2j+1][k] ), j: r 0-11, z 12-23, n 24-35
    __shared__ __align__(16) u64 Wp[HID][NP];          // 6912 B
    __shared__ __align__(16) ulonglong2 initRZ[24];    // ( W_ih pair, (b_ih+b_hh) pair )
    __shared__ __align__(16) ulonglong2 initN[12];     // ( W_ih_n pair, b_ih_n pair )
    __shared__ u64 bnhh[12];                           // b_hh n-gate pairs

    const int tid = threadIdx.x;
    for (int i = tid; i < HID * NP; i += TPB) {
        int k = i / NP, j = i % NP;
        Wp[k][j] = pack2(W_hh[(2*j) * HID + k], W_hh[(2*j+1) * HID + k]);
    }
    if (tid < 24) {
        int g = 2 * tid;
        initRZ[tid].x = pack2(W_ih[g], W_ih[g+1]);
        initRZ[tid].y = pack2(b_ih[g] + b_hh[g], b_ih[g+1] + b_hh[g+1]);
    } else if (tid < 36) {
        int j = tid - 24, g = 48 + 2 * j;
        initN[j].x = pack2(W_ih[g], W_ih[g+1]);
        initN[j].y = pack2(b_ih[g], b_ih[g+1]);
        bnhh[j]    = pack2(b_hh[g], b_hh[g+1]);
    }
    __syncthreads();

    // 2 threads per sequence: even lane = hidden units 0-11, odd = 12-23.
    const int s    = blockIdx.x * (TPB / 2) + (tid >> 1);
    const int half = tid & 1;
    if (s >= B) return;

    const int rb2 = 3 * half;        // ulonglong2 index of this thread's r pairs
    const int zb2 = 6 + 3 * half;    // z pairs
    const int nb2 = 12 + 3 * half;   // n pairs
    const int jr  = 6 * half;        // pair index base (r)
    const int jz  = 12 + 6 * half;   // (z)
    const int jn  = 6 * half;        // index into initN/bnhh (n)

    u64 h[12];                       // full replicated hidden state (12 pairs)
    #pragma unroll
    for (int p = 0; p < 12; p++) h[p] = 0ULL;

    const float* xrow = x + (long long)s * T;
    const u64 SGN2 = 0x8000000080000000ULL;

    for (int t = 0; t < T; t++) {
        const float xv = __ldg(xrow + t);
        const u64 x2 = pack2(xv, xv);

        u64 ar[6], az[6], an[6], xn[6];
        #pragma unroll
        for (int j = 0; j < 6; j++) {
            ulonglong2 wr = initRZ[jr + j];
            ar[j] = ffma2(wr.x, x2, wr.y);
            ulonglong2 wz = initRZ[jz + j];
            az[j] = ffma2(wz.x, x2, wz.y);
            ulonglong2 wn = initN[jn + j];
            xn[j] = ffma2(wn.x, x2, wn.y);
            an[j] = bnhh[jn + j];
        }

        // gh += W_hh . h  : 18 gate-pairs x 24 k = 432 FFMA2, 216 LDS.128
        #pragma unroll
        for (int p = 0; p < 12; p++) {
            float h0, h1; unpack2(h[p], h0, h1);
            const u64 ha = pack2(h0, h0);
            const u64 hb = pack2(h1, h1);
            {
                const ulonglong2* r0 = reinterpret_cast<const ulonglong2*>(&Wp[2*p][0]);
                #pragma unroll
                for (int j = 0; j < 3; j++) {
                    ulonglong2 w = r0[rb2 + j];
                    ar[2*j]   = ffma2(w.x, ha, ar[2*j]);
                    ar[2*j+1] = ffma2(w.y, ha, ar[2*j+1]);
                }
                #pragma unroll
                for (int j = 0; j < 3; j++) {
                    ulonglong2 w = r0[zb2 + j];
                    az[2*j]   = ffma2(w.x, ha, az[2*j]);
                    az[2*j+1] = ffma2(w.y, ha, az[2*j+1]);
                }
                #pragma unroll
                for (int j = 0; j < 3; j++) {
                    ulonglong2 w = r0[nb2 + j];
                    an[2*j]   = ffma2(w.x, ha, an[2*j]);
                    an[2*j+1] = ffma2(w.y, ha, an[2*j+1]);
                }
            }
            {
                const ulonglong2* r1 = reinterpret_cast<const ulonglong2*>(&Wp[2*p+1][0]);
                #pragma unroll
                for (int j = 0; j < 3; j++) {
                    ulonglong2 w = r1[rb2 + j];
                    ar[2*j]   = ffma2(w.x, hb, ar[2*j]);
                    ar[2*j+1] = ffma2(w.y, hb, ar[2*j+1]);
                }
                #pragma unroll
                for (int j = 0; j < 3; j++) {
                    ulonglong2 w = r1[zb2 + j];
                    az[2*j]   = ffma2(w.x, hb, az[2*j]);
                    az[2*j+1] = ffma2(w.y, hb, az[2*j+1]);
                }
                #pragma unroll
                for (int j = 0; j < 3; j++) {
                    ulonglong2 w = r1[nb2 + j];
                    an[2*j]   = ffma2(w.x, hb, an[2*j]);
                    an[2*j+1] = ffma2(w.y, hb, an[2*j+1]);
                }
            }
        }

        // gates + state update for this thread's 6 pairs
        u64 hown[6];
        #pragma unroll
        for (int j = 0; j < 6; j++) {
            float a0, a1; unpack2(ar[j], a0, a1);
            const u64 r2 = pack2(sig_f(a0), sig_f(a1));

            float c0, c1; unpack2(az[j], c0, c1);
            const u64 z2 = pack2(sig_f(c0), sig_f(c1));

            const u64 npre = ffma2(r2, an[j], xn[j]);
            float n0p, n1p; unpack2(npre, n0p, n1p);
            const u64 n2 = pack2(tanh_f(n0p), tanh_f(n1p));

            // h = n + z * (h - n)
            const u64 hp  = h[6*half + j];
            const u64 hmn = fadd2(hp, n2 ^ SGN2);
            hown[j] = ffma2(z2, hmn, n2);
        }

        // exchange halves with partner lane (lane ^ 1)
        #pragma unroll
        for (int j = 0; j < 6; j++) {
            u64 other = __shfl_xor_sync(0xFFFFFFFFu, hown[j], 1);
            h[6*half + j]       = hown[j];
            h[6*(1-half) + j]   = other;
        }
    }

    // final fc (even lane writes; it holds the full h)
    if (half == 0) {
        float hs[24];
        #pragma unroll
        for (int p = 0; p < 12; p++) unpack2(h[p], hs[2*p], hs[2*p+1]);
        float o0 = __ldg(fc_b + 0);
        float o1 = __ldg(fc_b + 1);
        #pragma unroll
        for (int k = 0; k < 24; k++) {
            o0 = fmaf(__ldg(fc_w + k),      hs[k], o0);
            o1 = fmaf(__ldg(fc_w + 24 + k), hs[k], o1);
        }
        out[2*s + 0] = o0;
        out[2*s + 1] = o1;
    }
}

extern "C" void kernel_launch(void* const* d_in, const int* in_sizes, int n_in,
                              void* d_out, int out_size)
{
    const float* x    = (const float*)d_in[0];
    const float* W_ih = (const float*)d_in[1];
    const float* b_ih = (const float*)d_in[2];
    const float* W_hh = (const float*)d_in[3];
    const float* b_hh = (const float*)d_in[4];
    const float* fc_w = (const float*)d_in[5];
    const float* fc_b = (const float*)d_in[6];
    float* out = (float*)d_out;

    const int B = out_size / 2;
    const int T = in_sizes[0] / B;

    const int seqs_per_block = TPB / 2;
    const int grid = (B + seqs_per_block - 1) / seqs_per_block;
    trendgru_kernel<<<grid, TPB>>>(x, W_ih, b_ih, W_hh, b_hh, fc_w, fc_b, out, B, T);
}

// round 3
// speedup vs baseline: 1.1535x; 1.1369x over previous
#include <cuda_runtime.h>

#define HID 24
#define TPB 64

typedef unsigned long long u64;

__device__ __forceinline__ u64 pack2(float x, float y) {
    u64 r; asm("mov.b64 %0, {%1, %2};" : "=l"(r) : "f"(x), "f"(y)); return r;
}
__device__ __forceinline__ void unpack2(u64 v, float &x, float &y) {
    asm("mov.b64 {%0, %1}, %2;" : "=f"(x), "=f"(y) : "l"(v));
}
__device__ __forceinline__ u64 ffma2(u64 a, u64 b, u64 c) {
    u64 d; asm("fma.rn.f32x2 %0, %1, %2, %3;" : "=l"(d) : "l"(a), "l"(b), "l"(c)); return d;
}
__device__ __forceinline__ u64 fadd2(u64 a, u64 b) {
    u64 d; asm("add.rn.f32x2 %0, %1, %2;" : "=l"(d) : "l"(a), "l"(b)); return d;
}
__device__ __forceinline__ float ex2a(float x) {
    float r; asm("ex2.approx.f32 %0, %1;" : "=f"(r) : "f"(x)); return r;
}
__device__ __forceinline__ float rcpa(float x) {
    float r; asm("rcp.approx.f32 %0, %1;" : "=f"(r) : "f"(x)); return r;
}
__device__ __forceinline__ float sig_f(float v) {
    return rcpa(1.0f + ex2a(v * -1.442695041f));
}
__device__ __forceinline__ float tanh_f(float v) {
    return fmaf(2.0f, rcpa(1.0f + ex2a(v * -2.885390082f)), -1.0f);
}

// Per-quarter weight block: 9 gate-pairs x 24 k, k-contiguous, padded to 220 u64
// so the 4 quarter blocks land on disjoint bank quads for every access pattern.
#define QSTRIDE 220

__global__ void __launch_bounds__(TPB, 7)
trendgru_kernel(const float* __restrict__ x,
                const float* __restrict__ W_ih,
                const float* __restrict__ b_ih,
                const float* __restrict__ W_hh,
                const float* __restrict__ b_hh,
                const float* __restrict__ fc_w,
                const float* __restrict__ fc_b,
                float* __restrict__ out,
                int B, int T)
{
    // Wq[q*220 + j*24 + k] = pack2(W_hh[row0][k], W_hh[row0+1][k]),
    //   j = gate*3+p (gate: 0=r,1=z,2=n), row0 = gate*24 + 6q + 2p
    __shared__ __align__(16) u64 Wq[4 * QSTRIDE];
    __shared__ __align__(16) ulonglong2 cRZ[4][6];  // (W_ih pair, b_ih+b_hh pair) r,z
    __shared__ __align__(16) ulonglong2 cN[4][3];   // (W_ih pair, b_ih pair) n
    __shared__ u64 cNH[4][3];                       // b_hh n pairs

    const int tid = threadIdx.x;
    for (int i = tid; i < 4 * 216; i += TPB) {
        int qq = i / 216, rem = i % 216;
        int j = rem / 24, k = rem % 24;
        int gate = j / 3, p = j % 3;
        int r0 = gate * 24 + 6 * qq + 2 * p;
        Wq[qq * QSTRIDE + j * 24 + k] = pack2(W_hh[r0 * HID + k], W_hh[(r0 + 1) * HID + k]);
    }
    if (tid < 24) {
        int qq = tid / 6, j2 = tid % 6;
        int gate = j2 / 3, p = j2 % 3;
        int r0 = gate * 24 + 6 * qq + 2 * p;
        cRZ[qq][j2].x = pack2(W_ih[r0], W_ih[r0 + 1]);
        cRZ[qq][j2].y = pack2(b_ih[r0] + b_hh[r0], b_ih[r0 + 1] + b_hh[r0 + 1]);
    }
    if (tid < 12) {
        int qq = tid / 3, p = tid % 3;
        int r0 = 48 + 6 * qq + 2 * p;
        cN[qq][p].x = pack2(W_ih[r0], W_ih[r0 + 1]);
        cN[qq][p].y = pack2(b_ih[r0], b_ih[r0 + 1]);
        cNH[qq][p]  = pack2(b_hh[r0], b_hh[r0 + 1]);
    }
    __syncthreads();

    // 4 threads per sequence-group, 2 sequences per thread.
    const int g     = blockIdx.x * TPB + tid;
    const int group = g >> 2;          // sequence group
    const int q     = tid & 3;         // quarter: hidden units [6q, 6q+6)
    const int s0    = group * 2;
    const int s1    = s0 + 1;

    u64 hA[3], hB[3];                  // own h pairs (units 6q..6q+5), per seq
    #pragma unroll
    for (int p = 0; p < 3; p++) { hA[p] = 0ULL; hB[p] = 0ULL; }

    const float* xr0 = x + (long long)s0 * T;
    const float* xr1 = x + (long long)s1 * T;
    const u64 SGN2 = 0x8000000080000000ULL;
    const u64* WqBase = &Wq[q * QSTRIDE];

    for (int t = 0; t < T; t++) {
        const float xv0 = __ldg(xr0 + t);
        const float xv1 = __ldg(xr1 + t);
        const u64 x2A = pack2(xv0, xv0);
        const u64 x2B = pack2(xv1, xv1);

        u64 accA[9], accB[9], xnA[3], xnB[3];
        #pragma unroll
        for (int j = 0; j < 6; j++) {           // r (0-2), z (3-5)
            ulonglong2 w = cRZ[q][j];
            accA[j] = ffma2(w.x, x2A, w.y);
            accB[j] = ffma2(w.x, x2B, w.y);
        }
        #pragma unroll
        for (int p = 0; p < 3; p++) {           // n
            ulonglong2 w = cN[q][p];
            xnA[p] = ffma2(w.x, x2A, w.y);
            xnB[p] = ffma2(w.x, x2B, w.y);
            u64 bv = cNH[q][p];
            accA[6 + p] = bv;
            accB[6 + p] = bv;
        }

        // matvec: iterate over the 4 quarter-sources of h
        #pragma unroll
        for (int s = 0; s < 4; s++) {
            const int srcq = q ^ s;
            u64 hsA[3], hsB[3];
            if (s == 0) {
                #pragma unroll
                for (int p = 0; p < 3; p++) { hsA[p] = hA[p]; hsB[p] = hB[p]; }
            } else {
                #pragma unroll
                for (int p = 0; p < 3; p++) {
                    hsA[p] = __shfl_xor_sync(0xFFFFFFFFu, hA[p], s);
                    hsB[p] = __shfl_xor_sync(0xFFFFFFFFu, hB[p], s);
                }
            }
            const ulonglong2* wrow =
                reinterpret_cast<const ulonglong2*>(WqBase + 6 * srcq);
            #pragma unroll
            for (int i = 0; i < 3; i++) {       // k pairs: kb+2i, kb+2i+1
                float a0, a1, b0, b1;
                unpack2(hsA[i], a0, a1);
                unpack2(hsB[i], b0, b1);
                const u64 ha0 = pack2(a0, a0), ha1 = pack2(a1, a1);
                const u64 hb0 = pack2(b0, b0), hb1 = pack2(b1, b1);
                #pragma unroll
                for (int j = 0; j < 9; j++) {
                    ulonglong2 w = wrow[j * 12 + i];   // (j*24 + 6srcq)/2 + i
                    accA[j] = ffma2(w.x, ha0, accA[j]);
                    accA[j] = ffma2(w.y, ha1, accA[j]);
                    accB[j] = ffma2(w.x, hb0, accB[j]);
                    accB[j] = ffma2(w.y, hb1, accB[j]);
                }
            }
        }

        // gates + state update (own 3 pairs, both seqs)
        #pragma unroll
        for (int p = 0; p < 3; p++) {
            {
                float a0, a1; unpack2(accA[p], a0, a1);
                const u64 r2 = pack2(sig_f(a0), sig_f(a1));
                float c0, c1; unpack2(accA[3 + p], c0, c1);
                const u64 z2 = pack2(sig_f(c0), sig_f(c1));
                const u64 npre = ffma2(r2, accA[6 + p], xnA[p]);
                float n0, n1; unpack2(npre, n0, n1);
                const u64 n2 = pack2(tanh_f(n0), tanh_f(n1));
                const u64 hmn = fadd2(hA[p], n2 ^ SGN2);
                hA[p] = ffma2(z2, hmn, n2);
            }
            {
                float a0, a1; unpack2(accB[p], a0, a1);
                const u64 r2 = pack2(sig_f(a0), sig_f(a1));
                float c0, c1; unpack2(accB[3 + p], c0, c1);
                const u64 z2 = pack2(sig_f(c0), sig_f(c1));
                const u64 npre = ffma2(r2, accB[6 + p], xnB[p]);
                float n0, n1; unpack2(npre, n0, n1);
                const u64 n2 = pack2(tanh_f(n0), tanh_f(n1));
                const u64 hmn = fadd2(hB[p], n2 ^ SGN2);
                hB[p] = ffma2(z2, hmn, n2);
            }
        }
    }

    // final fc: partial over own 6 hidden units, reduce across the 4-lane group
    float p0A = 0.f, p1A = 0.f, p0B = 0.f, p1B = 0.f;
    #pragma unroll
    for (int p = 0; p < 3; p++) {
        const int k = 6 * q + 2 * p;
        const float w00 = __ldg(fc_w + k),      w01 = __ldg(fc_w + k + 1);
        const float w10 = __ldg(fc_w + 24 + k), w11 = __ldg(fc_w + 24 + k + 1);
        float e0, e1;
        unpack2(hA[p], e0, e1);
        p0A += w00 * e0 + w01 * e1;
        p1A += w10 * e0 + w11 * e1;
        unpack2(hB[p], e0, e1);
        p0B += w00 * e0 + w01 * e1;
        p1B += w10 * e0 + w11 * e1;
    }
    #pragma unroll
    for (int off = 1; off < 4; off <<= 1) {
        p0A += __shfl_xor_sync(0xFFFFFFFFu, p0A, off);
        p1A += __shfl_xor_sync(0xFFFFFFFFu, p1A, off);
        p0B += __shfl_xor_sync(0xFFFFFFFFu, p0B, off);
        p1B += __shfl_xor_sync(0xFFFFFFFFu, p1B, off);
    }
    if (q == 0) {
        const float fb0 = __ldg(fc_b + 0), fb1 = __ldg(fc_b + 1);
        out[2 * s0 + 0] = p0A + fb0;
        out[2 * s0 + 1] = p1A + fb1;
        out[2 * s1 + 0] = p0B + fb0;
        out[2 * s1 + 1] = p1B + fb1;
    }
}

extern "C" void kernel_launch(void* const* d_in, const int* in_sizes, int n_in,
                              void* d_out, int out_size)
{
    const float* x    = (const float*)d_in[0];
    const float* W_ih = (const float*)d_in[1];
    const float* b_ih = (const float*)d_in[2];
    const float* W_hh = (const float*)d_in[3];
    const float* b_hh = (const float*)d_in[4];
    const float* fc_w = (const float*)d_in[5];
    const float* fc_b = (const float*)d_in[6];
    float* out = (float*)d_out;

    const int B = out_size / 2;
    const int T = in_sizes[0] / B;

    const int threads_total = (B / 2) * 4;   // 4 threads/seq, 2 seqs/thread
    const int grid = (threads_total + TPB - 1) / TPB;
    trendgru_kernel<<<grid, TPB>>>(x, W_ih, b_ih, W_hh, b_hh, fc_w, fc_b, out, B, T);
}

// round 5
// speedup vs baseline: 1.3172x; 1.1419x over previous
#include <cuda_runtime.h>

#define HID  24
#define TPB  128
#define NSEQ 4

typedef unsigned long long u64;

__device__ __forceinline__ u64 pack2(float x, float y) {
    u64 r; asm("mov.b64 %0, {%1, %2};" : "=l"(r) : "f"(x), "f"(y)); return r;
}
__device__ __forceinline__ void unpack2(u64 v, float &x, float &y) {
    asm("mov.b64 {%0, %1}, %2;" : "=f"(x), "=f"(y) : "l"(v));
}
__device__ __forceinline__ u64 ffma2(u64 a, u64 b, u64 c) {
    u64 d; asm("fma.rn.f32x2 %0, %1, %2, %3;" : "=l"(d) : "l"(a), "l"(b), "l"(c)); return d;
}
__device__ __forceinline__ u64 fadd2(u64 a, u64 b) {
    u64 d; asm("add.rn.f32x2 %0, %1, %2;" : "=l"(d) : "l"(a), "l"(b)); return d;
}
__device__ __forceinline__ float ex2a(float x) {
    float r; asm("ex2.approx.f32 %0, %1;" : "=f"(r) : "f"(x)); return r;
}
__device__ __forceinline__ float rcpa(float x) {
    float r; asm("rcp.approx.f32 %0, %1;" : "=f"(r) : "f"(x)); return r;
}
__device__ __forceinline__ float sig_f(float v) {
    return rcpa(1.0f + ex2a(v * -1.442695041f));
}
__device__ __forceinline__ float tanh_f(float v) {
    return fmaf(2.0f, rcpa(1.0f + ex2a(v * -2.885390082f)), -1.0f);
}

// Per-quarter weight block: 9 gate-pairs x 24 k, padded to 220 u64 so the 4
// quarter blocks hit disjoint bank quads for every (source, j, i) pattern.
#define QSTRIDE 220

__global__ void __launch_bounds__(TPB)
trendgru_kernel(const float* __restrict__ x,
                const float* __restrict__ W_ih,
                const float* __restrict__ b_ih,
                const float* __restrict__ W_hh,
                const float* __restrict__ b_hh,
                const float* __restrict__ fc_w,
                const float* __restrict__ fc_b,
                float* __restrict__ out,
                int B, int T)
{
    // Wq[q*220 + j*24 + k] = pack2(W_hh[row0][k], W_hh[row0+1][k]),
    //   j = gate*3+p (gate: 0=r,1=z,2=n), row0 = gate*24 + 6q + 2p
    __shared__ __align__(16) u64 Wq[4 * QSTRIDE];
    __shared__ __align__(16) ulonglong2 cRZ[4][6];  // (W_ih pair, b_ih+b_hh pair)
    __shared__ __align__(16) ulonglong2 cN[4][3];   // (W_ih pair, b_ih pair)
    __shared__ u64 cNH[4][3];                       // b_hh n pairs

    const int tid = threadIdx.x;
    for (int i = tid; i < 4 * 216; i += TPB) {
        int qq = i / 216, rem = i % 216;
        int j = rem / 24, k = rem % 24;
        int gate = j / 3, p = j % 3;
        int r0 = gate * 24 + 6 * qq + 2 * p;
        Wq[qq * QSTRIDE + j * 24 + k] = pack2(W_hh[r0 * HID + k], W_hh[(r0 + 1) * HID + k]);
    }
    if (tid < 24) {
        int qq = tid / 6, j2 = tid % 6;
        int gate = j2 / 3, p = j2 % 3;
        int r0 = gate * 24 + 6 * qq + 2 * p;
        cRZ[qq][j2].x = pack2(W_ih[r0], W_ih[r0 + 1]);
        cRZ[qq][j2].y = pack2(b_ih[r0] + b_hh[r0], b_ih[r0 + 1] + b_hh[r0 + 1]);
    }
    if (tid < 12) {
        int qq = tid / 3, p = tid % 3;
        int r0 = 48 + 6 * qq + 2 * p;
        cN[qq][p].x = pack2(W_ih[r0], W_ih[r0 + 1]);
        cN[qq][p].y = pack2(b_ih[r0], b_ih[r0 + 1]);
        cNH[qq][p]  = pack2(b_hh[r0], b_hh[r0 + 1]);
    }
    __syncthreads();

    // 4 threads per sequence-group, NSEQ sequences per thread.
    const int g     = blockIdx.x * TPB + tid;
    const int group = g >> 2;
    const int q     = tid & 3;          // hidden units [6q, 6q+6)
    const int s0    = group * NSEQ;

    u64 h[NSEQ][3];
    #pragma unroll
    for (int m = 0; m < NSEQ; m++)
        #pragma unroll
        for (int p = 0; p < 3; p++) h[m][p] = 0ULL;

    const float* xbase = x + (size_t)s0 * T;
    const u64 SGN2 = 0x8000000080000000ULL;
    const u64* WqBase = &Wq[q * QSTRIDE];

    for (int t = 0; t < T; t++) {
        u64 x2[NSEQ];
        #pragma unroll
        for (int m = 0; m < NSEQ; m++) {
            const float xv = __ldg(xbase + (size_t)m * T + t);
            x2[m] = pack2(xv, xv);
        }

        u64 acc[NSEQ][9], xn[NSEQ][3];
        #pragma unroll
        for (int j = 0; j < 6; j++) {           // r (0-2), z (3-5)
            ulonglong2 w = cRZ[q][j];
            #pragma unroll
            for (int m = 0; m < NSEQ; m++)
                acc[m][j] = ffma2(w.x, x2[m], w.y);
        }
        #pragma unroll
        for (int p = 0; p < 3; p++) {           // n
            ulonglong2 w = cN[q][p];
            u64 bv = cNH[q][p];
            #pragma unroll
            for (int m = 0; m < NSEQ; m++) {
                xn[m][p]     = ffma2(w.x, x2[m], w.y);
                acc[m][6+p]  = bv;
            }
        }

        // matvec over the 4 quarter-sources of h
        #pragma unroll
        for (int s = 0; s < 4; s++) {
            const int srcq = q ^ s;
            u64 hs[NSEQ][3];
            if (s == 0) {
                #pragma unroll
                for (int m = 0; m < NSEQ; m++)
                    #pragma unroll
                    for (int p = 0; p < 3; p++) hs[m][p] = h[m][p];
            } else {
                #pragma unroll
                for (int m = 0; m < NSEQ; m++)
                    #pragma unroll
                    for (int p = 0; p < 3; p++)
                        hs[m][p] = __shfl_xor_sync(0xFFFFFFFFu, h[m][p], s);
            }
            const ulonglong2* wrow =
                reinterpret_cast<const ulonglong2*>(WqBase + 6 * srcq);
            #pragma unroll
            for (int i = 0; i < 3; i++) {
                u64 e0[NSEQ], e1[NSEQ];
                #pragma unroll
                for (int m = 0; m < NSEQ; m++) {
                    float a0, a1; unpack2(hs[m][i], a0, a1);
                    e0[m] = pack2(a0, a0);
                    e1[m] = pack2(a1, a1);
                }
                #pragma unroll
                for (int j = 0; j < 9; j++) {
                    ulonglong2 w = wrow[j * 12 + i];
                    #pragma unroll
                    for (int m = 0; m < NSEQ; m++) {
                        acc[m][j] = ffma2(w.x, e0[m], acc[m][j]);
                        acc[m][j] = ffma2(w.y, e1[m], acc[m][j]);
                    }
                }
            }
        }

        // gates + state update
        #pragma unroll
        for (int m = 0; m < NSEQ; m++) {
            #pragma unroll
            for (int p = 0; p < 3; p++) {
                float a0, a1; unpack2(acc[m][p], a0, a1);
                const u64 r2 = pack2(sig_f(a0), sig_f(a1));
                float c0, c1; unpack2(acc[m][3 + p], c0, c1);
                const u64 z2 = pack2(sig_f(c0), sig_f(c1));
                const u64 npre = ffma2(r2, acc[m][6 + p], xn[m][p]);
                float n0, n1; unpack2(npre, n0, n1);
                const u64 n2 = pack2(tanh_f(n0), tanh_f(n1));
                const u64 hmn = fadd2(h[m][p], n2 ^ SGN2);
                h[m][p] = ffma2(z2, hmn, n2);
            }
        }
    }

    // final fc: partials over own 6 hidden units, reduce across 4-lane group
    float p0[NSEQ], p1[NSEQ];
    #pragma unroll
    for (int m = 0; m < NSEQ; m++) { p0[m] = 0.f; p1[m] = 0.f; }
    #pragma unroll
    for (int p = 0; p < 3; p++) {
        const int k = 6 * q + 2 * p;
        const float w00 = __ldg(fc_w + k),      w01 = __ldg(fc_w + k + 1);
        const float w10 = __ldg(fc_w + 24 + k), w11 = __ldg(fc_w + 24 + k + 1);
        #pragma unroll
        for (int m = 0; m < NSEQ; m++) {
            float e0, e1; unpack2(h[m][p], e0, e1);
            p0[m] += w00 * e0 + w01 * e1;
            p1[m] += w10 * e0 + w11 * e1;
        }
    }
    #pragma unroll
    for (int off = 1; off < 4; off <<= 1) {
        #pragma unroll
        for (int m = 0; m < NSEQ; m++) {
            p0[m] += __shfl_xor_sync(0xFFFFFFFFu, p0[m], off);
            p1[m] += __shfl_xor_sync(0xFFFFFFFFu, p1[m], off);
        }
    }
    if (q == 0) {
        const float fb0 = __ldg(fc_b + 0), fb1 = __ldg(fc_b + 1);
        #pragma unroll
        for (int m = 0; m < NSEQ; m++) {
            out[2 * (s0 + m) + 0] = p0[m] + fb0;
            out[2 * (s0 + m) + 1] = p1[m] + fb1;
        }
    }
}

extern "C" void kernel_launch(void* const* d_in, const int* in_sizes, int n_in,
                              void* d_out, int out_size)
{
    const float* x    = (const float*)d_in[0];
    const float* W_ih = (const float*)d_in[1];
    const float* b_ih = (const float*)d_in[2];
    const float* W_hh = (const float*)d_in[3];
    const float* b_hh = (const float*)d_in[4];
    const float* fc_w = (const float*)d_in[5];
    const float* fc_b = (const float*)d_in[6];
    float* out = (float*)d_out;

    const int B = out_size / 2;
    const int T = in_sizes[0] / B;

    const int threads_total = (B / NSEQ) * 4;   // 4 threads/seq, NSEQ seqs/thread
    const int grid = (threads_total + TPB - 1) / TPB;
    trendgru_kernel<<<grid, TPB>>>(x, W_ih, b_ih, W_hh, b_hh, fc_w, fc_b, out, B, T);
}

// round 6
// speedup vs baseline: 1.3341x; 1.0128x over previous
#include <cuda_runtime.h>

#define HID 24
#define TPB 64
#define WSTRIDE 114   // 108 u64 payload + 6 pad: 2*114 mod 32 = 4 -> 8 blocks on disjoint bank quads

typedef unsigned long long u64;

__device__ __forceinline__ u64 pack2(float x, float y) {
    u64 r; asm("mov.b64 %0, {%1, %2};" : "=l"(r) : "f"(x), "f"(y)); return r;
}
__device__ __forceinline__ void unpack2(u64 v, float &x, float &y) {
    asm("mov.b64 {%0, %1}, %2;" : "=f"(x), "=f"(y) : "l"(v));
}
__device__ __forceinline__ u64 ffma2(u64 a, u64 b, u64 c) {
    u64 d; asm("fma.rn.f32x2 %0, %1, %2, %3;" : "=l"(d) : "l"(a), "l"(b), "l"(c)); return d;
}
__device__ __forceinline__ u64 fmul2(u64 a, u64 b) {
    u64 d; asm("mul.rn.f32x2 %0, %1, %2;" : "=l"(d) : "l"(a), "l"(b)); return d;
}
__device__ __forceinline__ u64 fadd2(u64 a, u64 b) {
    u64 d; asm("add.rn.f32x2 %0, %1, %2;" : "=l"(d) : "l"(a), "l"(b)); return d;
}
__device__ __forceinline__ float ex2a(float x) {
    float r; asm("ex2.approx.f32 %0, %1;" : "=f"(r) : "f"(x)); return r;
}
__device__ __forceinline__ float rcpa(float x) {
    float r; asm("rcp.approx.f32 %0, %1;" : "=f"(r) : "f"(x)); return r;
}

__global__ void __launch_bounds__(TPB, 7)
trendgru_kernel(const float* __restrict__ x,
                const float* __restrict__ W_ih,
                const float* __restrict__ b_ih,
                const float* __restrict__ W_hh,
                const float* __restrict__ b_hh,
                const float* __restrict__ fc_w,
                const float* __restrict__ fc_b,
                float* __restrict__ out,
                int B, int T)
{
    // Wk block b = q*2 + kg : Wk[b*114 + j*12 + kk] = (W_hh[r0][u], W_hh[r0+1][u])
    //   j = gate*3+p (rows r0 = gate*24 + 6q + 2p), u = 12*kg + kk
    __shared__ __align__(16) u64 Wk[8 * WSTRIDE];
    __shared__ __align__(16) ulonglong2 cRZ[4][6];  // (W_ih pair, b_ih+b_hh pair)
    __shared__ __align__(16) ulonglong2 cN[4][3];   // (W_ih pair, b_ih pair)
    __shared__ u64 cNH[4][3];                       // b_hh n pairs

    const int tid = threadIdx.x;
    for (int i = tid; i < 8 * 108; i += TPB) {
        int bb = i / 108, rem = i % 108;
        int j = rem / 12, kk = rem % 12;
        int qq = bb >> 1, kgg = bb & 1;
        int gate = j / 3, p = j % 3;
        int r0 = gate * 24 + 6 * qq + 2 * p;
        int u = 12 * kgg + kk;
        Wk[bb * WSTRIDE + j * 12 + kk] = pack2(W_hh[r0 * HID + u], W_hh[(r0 + 1) * HID + u]);
    }
    if (tid < 24) {
        int qq = tid / 6, j6 = tid % 6;
        int gate = j6 / 3, p = j6 % 3;
        int r0 = gate * 24 + 6 * qq + 2 * p;
        cRZ[qq][j6].x = pack2(W_ih[r0], W_ih[r0 + 1]);
        cRZ[qq][j6].y = pack2(b_ih[r0] + b_hh[r0], b_ih[r0 + 1] + b_hh[r0 + 1]);
    }
    if (tid < 12) {
        int qq = tid / 3, p = tid % 3;
        int r0 = 48 + 6 * qq + 2 * p;
        cN[qq][p].x = pack2(W_ih[r0], W_ih[r0 + 1]);
        cN[qq][p].y = pack2(b_ih[r0], b_ih[r0 + 1]);
        cNH[qq][p]  = pack2(b_hh[r0], b_hh[r0 + 1]);
    }
    __syncthreads();

    // lane layout: cohort = lane>>3 (4 seqs each), q = lane&3 (gate quarter),
    // half = (lane>>2)&1 (k-half). kgroup this thread multiplies: (q>>1)^half.
    const int lane   = tid & 31;
    const int cohort = lane >> 3;
    const int q      = lane & 3;
    const int half   = (lane >> 2) & 1;
    const int kg     = (q >> 1) ^ half;
    const u64* wbase = &Wk[(q * 2 + kg) * WSTRIDE];

    const int gcoh  = (blockIdx.x * TPB + tid) >> 3;
    const int sbase = gcoh * 4;
    // gate-owner seqs (slots 0,1): sbase + 2*half + {0,1}
    const float* xr0 = x + (size_t)(sbase + 2 * half) * T;
    const float* xr1 = xr0 + T;

    u64 hown[2][3];     // own h pairs (units 6q..6q+5) for slots 0,1
    #pragma unroll
    for (int mo = 0; mo < 2; mo++)
        #pragma unroll
        for (int p = 0; p < 3; p++) hown[mo][p] = 0ULL;

    for (int t = 0; t < T; t++) {
        const float xa = __ldg(xr0 + t);
        const float xb = __ldg(xr1 + t);
        u64 x2[2];
        x2[0] = pack2(xa, xa);
        x2[1] = pack2(xb, xb);

        u64 acc[4][9];

        // ---- matvec partials over this thread's 12 k-units, all 4 seq slots
        #pragma unroll
        for (int i = 0; i < 6; i++) {
            const int p = i % 3;
            const int srcq = 2 * kg + ((i >= 3) ? 1 : 0);
            u64 e0[4], e1[4];
            #pragma unroll
            for (int m = 0; m < 4; m++) {
                const int mo = m & 1;
                const int hs = half ^ (m >> 1);
                const int src = 8 * cohort + srcq + 4 * hs;
                const u64 hv = __shfl_sync(0xFFFFFFFFu, hown[mo][p], src);
                float h0, h1; unpack2(hv, h0, h1);
                e0[m] = pack2(h0, h0);
                e1[m] = pack2(h1, h1);
            }
            #pragma unroll
            for (int j = 0; j < 9; j++) {
                const ulonglong2 w =
                    *reinterpret_cast<const ulonglong2*>(wbase + j * 12 + 2 * i);
                #pragma unroll
                for (int m = 0; m < 4; m++) {
                    if (i == 0)
                        acc[m][j] = ffma2(w.y, e1[m], fmul2(w.x, e0[m]));
                    else
                        acc[m][j] = ffma2(w.x, e0[m], ffma2(w.y, e1[m], acc[m][j]));
                }
            }
        }

        // ---- reduce k-halves: my slots 0,1 <- + partner's slots 2,3
        #pragma unroll
        for (int j = 0; j < 9; j++)
            #pragma unroll
            for (int mo = 0; mo < 2; mo++)
                acc[mo][j] = fadd2(acc[mo][j],
                                   __shfl_xor_sync(0xFFFFFFFFu, acc[2 + mo][j], 4));

        // ---- gates + h update for slots 0,1 (own units)
        #pragma unroll
        for (int mo = 0; mo < 2; mo++) {
            #pragma unroll
            for (int p = 0; p < 3; p++) {
                const ulonglong2 wr = cRZ[q][p];
                const u64 rpre = fadd2(acc[mo][p],     ffma2(wr.x, x2[mo], wr.y));
                const ulonglong2 wz = cRZ[q][3 + p];
                const u64 zpre = fadd2(acc[mo][3 + p], ffma2(wz.x, x2[mo], wz.y));
                const u64 hn   = fadd2(acc[mo][6 + p], cNH[q][p]);
                const ulonglong2 wn = cN[q][p];
                const u64 xn   = ffma2(wn.x, x2[mo], wn.y);

                float a0, a1, c0, c1;
                unpack2(rpre, a0, a1);
                unpack2(zpre, c0, c1);
                const float A = 1.0f + ex2a(a0 * -1.442695041f);
                const float Bv = 1.0f + ex2a(a1 * -1.442695041f);
                const float C = 1.0f + ex2a(c0 * -1.442695041f);
                const float D = 1.0f + ex2a(c1 * -1.442695041f);
                const float AB = A * Bv, CD = C * D;
                const float R  = rcpa(AB * CD);
                const float r0 = R * (Bv * CD);
                const float r1 = R * (A * CD);
                const float z0 = R * (AB * D);
                const float z1 = R * (AB * C);

                float hn0, hn1, xn0, xn1;
                unpack2(hn, hn0, hn1);
                unpack2(xn, xn0, xn1);
                const float an0 = fmaf(r0, hn0, xn0);
                const float an1 = fmaf(r1, hn1, xn1);
                const float g0 = 1.0f + ex2a(an0 * -2.885390082f);
                const float g1 = 1.0f + ex2a(an1 * -2.885390082f);
                const float rq = rcpa(g0 * g1);
                const float n0 = fmaf(2.0f * rq, g1, -1.0f);
                const float n1 = fmaf(2.0f * rq, g0, -1.0f);

                float ho0, ho1; unpack2(hown[mo][p], ho0, ho1);
                const float hN0 = fmaf(z0, ho0 - n0, n0);
                const float hN1 = fmaf(z1, ho1 - n1, n1);
                hown[mo][p] = pack2(hN0, hN1);
            }
        }
    }

    // ---- final fc: partials over own 6 units for slots 0,1; reduce over q lanes
    float p00 = 0.f, p01 = 0.f, p10 = 0.f, p11 = 0.f;   // [slot][out]
    #pragma unroll
    for (int p = 0; p < 3; p++) {
        const int k = 6 * q + 2 * p;
        const float w00 = __ldg(fc_w + k),      w01 = __ldg(fc_w + k + 1);
        const float w10 = __ldg(fc_w + 24 + k), w11 = __ldg(fc_w + 24 + k + 1);
        float e0, e1;
        unpack2(hown[0][p], e0, e1);
        p00 += w00 * e0 + w01 * e1;
        p01 += w10 * e0 + w11 * e1;
        unpack2(hown[1][p], e0, e1);
        p10 += w00 * e0 + w01 * e1;
        p11 += w10 * e0 + w11 * e1;
    }
    #pragma unroll
    for (int off = 1; off < 4; off <<= 1) {   // xor 1,2: stays within same half
        p00 += __shfl_xor_sync(0xFFFFFFFFu, p00, off);
        p01 += __shfl_xor_sync(0xFFFFFFFFu, p01, off);
        p10 += __shfl_xor_sync(0xFFFFFFFFu, p10, off);
        p11 += __shfl_xor_sync(0xFFFFFFFFu, p11, off);
    }
    if (q == 0) {
        const float fb0 = __ldg(fc_b + 0), fb1 = __ldg(fc_b + 1);
        const int sA = sbase + 2 * half;
        out[2 * sA + 0] = p00 + fb0;
        out[2 * sA + 1] = p01 + fb1;
        out[2 * sA + 2] = p10 + fb0;
        out[2 * sA + 3] = p11 + fb1;
    }
}

extern "C" void kernel_launch(void* const* d_in, const int* in_sizes, int n_in,
                              void* d_out, int out_size)
{
    const float* x    = (const float*)d_in[0];
    const float* W_ih = (const float*)d_in[1];
    const float* b_ih = (const float*)d_in[2];
    const float* W_hh = (const float*)d_in[3];
    const float* b_hh = (const float*)d_in[4];
    const float* fc_w = (const float*)d_in[5];
    const float* fc_b = (const float*)d_in[6];
    float* out = (float*)d_out;

    const int B = out_size / 2;
    const int T = in_sizes[0] / B;

    const int threads_total = (B / 4) * 8;    // 8 threads/seq, 4 seqs per 8-thread cohort
    const int grid = threads_total / TPB;
    trendgru_kernel<<<grid, TPB>>>(x, W_ih, b_ih, W_hh, b_hh, fc_w, fc_b, out, B, T);
}